// round 1
// baseline (speedup 1.0000x reference)
#include <cuda_runtime.h>
#include <math.h>

// Problem constants
#define PB 8
#define PN 1024
#define PC 768
#define PH 8
#define PD 96
#define PM 1024

// Scratch (device globals — no runtime allocation)
__device__ float  g_q[(size_t)PB*PN*PC];
__device__ float  g_k[(size_t)PB*PN*PC];
__device__ float  g_v[(size_t)PB*PN*PC];
__device__ float  g_S[(size_t)PB*PH*PN*PM];   // QK^T scores, then mixed pre-BN attn (in place)
__device__ float  g_oh[(size_t)PB*PN*PC];     // attn_norm @ V, layout (b,g,n,d)
__device__ double g_stats[16];                // sum[8], sumsq[8]
__device__ float  g_norm[16];                 // A[g]=invstd*gamma, B[g]=beta-mean*A

// ---------------------------------------------------------------------------
__global__ void zero_stats_kernel() {
    if (threadIdx.x < 16) g_stats[threadIdx.x] = 0.0;
}

// ---------------------------------------------------------------------------
// Per-token 3x3 SAME convs (3->3 ch) on 3x16x16 images; one block per image.
__global__ void conv_qkv_kernel(const float* __restrict__ x,
                                const float* __restrict__ wq,
                                const float* __restrict__ wk,
                                const float* __restrict__ wv) {
    __shared__ float simg[3][16][16];
    __shared__ float sw[3][81];
    int img = blockIdx.x;
    int tid = threadIdx.x;
    for (int e = tid; e < 768; e += 256)
        ((float*)simg)[e] = x[(size_t)img * 768 + e];
    if (tid < 81) { sw[0][tid] = wq[tid]; sw[1][tid] = wk[tid]; sw[2][tid] = wv[tid]; }
    __syncthreads();
    int i = tid >> 4, j = tid & 15;
    float out[3][3];
    #pragma unroll
    for (int a = 0; a < 3; a++)
        #pragma unroll
        for (int c = 0; c < 3; c++) out[a][c] = 0.f;
    #pragma unroll
    for (int ci = 0; ci < 3; ci++)
        #pragma unroll
        for (int di = 0; di < 3; di++) {
            int ii = i + di - 1;
            if (ii < 0 || ii > 15) continue;
            #pragma unroll
            for (int dj = 0; dj < 3; dj++) {
                int jj = j + dj - 1;
                if (jj < 0 || jj > 15) continue;
                float pix = simg[ci][ii][jj];
                int wi = ci * 9 + di * 3 + dj;
                #pragma unroll
                for (int co = 0; co < 3; co++) {
                    out[0][co] += pix * sw[0][co * 27 + wi];
                    out[1][co] += pix * sw[1][co * 27 + wi];
                    out[2][co] += pix * sw[2][co * 27 + wi];
                }
            }
        }
    #pragma unroll
    for (int co = 0; co < 3; co++) {
        int c = co * 256 + i * 16 + j;
        size_t o = (size_t)img * 768 + c;
        g_q[o] = out[0][co];
        g_k[o] = out[1][co];
        g_v[o] = out[2][co];
    }
}

// ---------------------------------------------------------------------------
// S[b,h,n,m] = scale * sum_d q[b,n,h*96+d] * k[b,m,h*96+d]
// Tiles 64x64, K-chunks of 32, 4x4 micro-tile per thread.
__global__ void qk_gemm_kernel() {
    __shared__ float a_s[32][65];
    __shared__ float b_s[32][65];
    int mt = blockIdx.x, nt = blockIdx.y, bh = blockIdx.z;
    int b = bh >> 3, h = bh & 7;
    int tid = threadIdx.x;
    int tx = tid & 15, ty = tid >> 4;
    const float* qb = g_q + (size_t)b * PN * PC + h * PD;
    const float* kb = g_k + (size_t)b * PN * PC + h * PD;
    int n0 = nt * 64, m0 = mt * 64;
    float acc[4][4] = {};
    for (int kc = 0; kc < PD; kc += 32) {
        #pragma unroll
        for (int l = 0; l < 8; l++) {
            int e = tid + l * 256;
            int row = e >> 5, col = e & 31;
            a_s[col][row] = qb[(size_t)(n0 + row) * PC + kc + col];
            b_s[col][row] = kb[(size_t)(m0 + row) * PC + kc + col];
        }
        __syncthreads();
        #pragma unroll
        for (int kk = 0; kk < 32; kk++) {
            float a[4], bb[4];
            #pragma unroll
            for (int i2 = 0; i2 < 4; i2++) a[i2] = a_s[kk][ty * 4 + i2];
            #pragma unroll
            for (int j2 = 0; j2 < 4; j2++) bb[j2] = b_s[kk][tx * 4 + j2];
            #pragma unroll
            for (int i2 = 0; i2 < 4; i2++)
                #pragma unroll
                for (int j2 = 0; j2 < 4; j2++) acc[i2][j2] += a[i2] * bb[j2];
        }
        __syncthreads();
    }
    const float scale = 0.10206207261596577f;  // 96^-0.5
    float* Sb = g_S + ((size_t)bh * PN + n0) * PM + m0;
    #pragma unroll
    for (int i2 = 0; i2 < 4; i2++)
        #pragma unroll
        for (int j2 = 0; j2 < 4; j2++)
            Sb[(size_t)(ty * 4 + i2) * PM + tx * 4 + j2] = acc[i2][j2] * scale;
}

// ---------------------------------------------------------------------------
// One block per (b,n): softmax over m for all 8 heads (rows in smem),
// head-mix (8x8) + bias, write mixed pre-BN attn back into g_S IN PLACE
// (this block owns exactly rows (b,*,n,*)), accumulate BN stats (fp64 atomics).
__global__ void softmax_mix_kernel(const float* __restrict__ rw,
                                   const float* __restrict__ rb) {
    __shared__ float p[8][1024];
    __shared__ float wred[8];
    __shared__ float sval;
    __shared__ float sinv[8];
    __shared__ float wsc[8][8];
    __shared__ float sb[8];
    __shared__ float ssum[8], ssq[8];
    int bn = blockIdx.x;
    int b = bn >> 10, n = bn & 1023;
    int tid = threadIdx.x;
    int lane = tid & 31, warp = tid >> 5;
    if (tid < 8) { sb[tid] = rb[tid]; ssum[tid] = 0.f; ssq[tid] = 0.f; }
    #pragma unroll
    for (int h = 0; h < 8; h++) {
        size_t o = (((size_t)(b * 8 + h)) * PN + n) * PM;
        #pragma unroll
        for (int l = 0; l < 4; l++) p[h][tid + l * 256] = g_S[o + tid + l * 256];
    }
    __syncthreads();
    for (int h = 0; h < 8; h++) {
        float mx = -1e30f;
        #pragma unroll
        for (int l = 0; l < 4; l++) mx = fmaxf(mx, p[h][tid + l * 256]);
        #pragma unroll
        for (int off = 16; off; off >>= 1)
            mx = fmaxf(mx, __shfl_down_sync(0xffffffffu, mx, off));
        if (lane == 0) wred[warp] = mx;
        __syncthreads();
        if (tid == 0) {
            float m2 = wred[0];
            for (int w = 1; w < 8; w++) m2 = fmaxf(m2, wred[w]);
            sval = m2;
        }
        __syncthreads();
        float rowmax = sval;
        float s = 0.f;
        #pragma unroll
        for (int l = 0; l < 4; l++) {
            float e = expf(p[h][tid + l * 256] - rowmax);
            p[h][tid + l * 256] = e;
            s += e;
        }
        #pragma unroll
        for (int off = 16; off; off >>= 1) s += __shfl_down_sync(0xffffffffu, s, off);
        if (lane == 0) wred[warp] = s;
        __syncthreads();
        if (tid == 0) {
            float t = 0.f;
            for (int w = 0; w < 8; w++) t += wred[w];
            sinv[h] = 1.f / t;
        }
        __syncthreads();
    }
    if (tid < 64) wsc[tid >> 3][tid & 7] = rw[tid] * sinv[tid & 7];
    __syncthreads();
    float ls[8], lq[8];
    #pragma unroll
    for (int g = 0; g < 8; g++) { ls[g] = 0.f; lq[g] = 0.f; }
    #pragma unroll
    for (int l = 0; l < 4; l++) {
        int m = tid + l * 256;
        float pv[8];
        #pragma unroll
        for (int h = 0; h < 8; h++) pv[h] = p[h][m];
        #pragma unroll
        for (int g = 0; g < 8; g++) {
            float acc = sb[g];
            #pragma unroll
            for (int h = 0; h < 8; h++) acc += wsc[g][h] * pv[h];
            g_S[(((size_t)(b * 8 + g)) * PN + n) * PM + m] = acc;
            ls[g] += acc;
            lq[g] += acc * acc;
        }
    }
    #pragma unroll
    for (int g = 0; g < 8; g++) {
        float s1 = ls[g], s2 = lq[g];
        #pragma unroll
        for (int off = 16; off; off >>= 1) {
            s1 += __shfl_down_sync(0xffffffffu, s1, off);
            s2 += __shfl_down_sync(0xffffffffu, s2, off);
        }
        if (lane == 0) { atomicAdd(&ssum[g], s1); atomicAdd(&ssq[g], s2); }
    }
    __syncthreads();
    if (tid < 8) {
        atomicAdd(&g_stats[tid], (double)ssum[tid]);
        atomicAdd(&g_stats[8 + tid], (double)ssq[tid]);
    }
}

// ---------------------------------------------------------------------------
__global__ void finalize_kernel(const float* __restrict__ gamma,
                                const float* __restrict__ beta) {
    int g = threadIdx.x;
    if (g < 8) {
        double cnt = 8388608.0;  // B*N*M
        double mean = g_stats[g] / cnt;
        double var = g_stats[8 + g] / cnt - mean * mean;
        double invstd = rsqrt(var + 1e-5);
        double A = invstd * (double)gamma[g];
        g_norm[g] = (float)A;
        g_norm[8 + g] = (float)((double)beta[g] - mean * A);
    }
}

// ---------------------------------------------------------------------------
// Normalize-on-load BN + attn@V. One block per (n-tile, b*8+g); tile 64n x 96d,
// m-chunks of 64. Writes normalized attn to d_out attn region; out to g_oh.
__global__ void bn_av_kernel(float* __restrict__ attn_out) {
    __shared__ float a_s[64][65];
    __shared__ float v_s[64][96];
    int nt = blockIdx.x, bg = blockIdx.y;
    int b = bg >> 3, g = bg & 7;
    int tid = threadIdx.x, tx = tid & 15, ty = tid >> 4;
    float A = g_norm[g], Bc = g_norm[8 + g];
    const float* Sb = g_S + (size_t)bg * PN * PM;
    float* aoB = attn_out + (size_t)bg * PN * PM;
    const float* vB = g_v + (size_t)b * PN * PC + g * PD;
    int n0 = nt * 64;
    float acc[4][6] = {};
    for (int m0 = 0; m0 < PM; m0 += 64) {
        #pragma unroll
        for (int l = 0; l < 16; l++) {
            int e = tid + l * 256;
            int nr = e >> 6, mc = e & 63;
            size_t gi = (size_t)(n0 + nr) * PM + m0 + mc;
            float nv = Sb[gi] * A + Bc;
            aoB[gi] = nv;
            a_s[mc][nr] = nv;
        }
        #pragma unroll
        for (int l = 0; l < 24; l++) {
            int e = tid + l * 256;
            int mr = e / 96, dc = e % 96;
            v_s[mr][dc] = vB[(size_t)(m0 + mr) * PC + dc];
        }
        __syncthreads();
        #pragma unroll
        for (int kk = 0; kk < 64; kk++) {
            float a[4], vv[6];
            #pragma unroll
            for (int i2 = 0; i2 < 4; i2++) a[i2] = a_s[kk][ty * 4 + i2];
            #pragma unroll
            for (int j2 = 0; j2 < 6; j2++) vv[j2] = v_s[kk][tx * 6 + j2];
            #pragma unroll
            for (int i2 = 0; i2 < 4; i2++)
                #pragma unroll
                for (int j2 = 0; j2 < 6; j2++) acc[i2][j2] += a[i2] * vv[j2];
        }
        __syncthreads();
    }
    float* ohB = g_oh + ((size_t)bg * PN + n0) * PD;
    #pragma unroll
    for (int i2 = 0; i2 < 4; i2++)
        #pragma unroll
        for (int j2 = 0; j2 < 6; j2++)
            ohB[(size_t)(ty * 4 + i2) * PD + tx * 6 + j2] = acc[i2][j2];
}

// ---------------------------------------------------------------------------
// out[b,n,c] = sum_k oh[b, k/96, n, k%96] * pw[c,k] + pb[c]
__global__ void proj_kernel(const float* __restrict__ pw,
                            const float* __restrict__ pb,
                            float* __restrict__ out) {
    __shared__ float a_s[32][65];
    __shared__ float w_s[32][65];
    int ct = blockIdx.x, rt = blockIdx.y;
    int tid = threadIdx.x, tx = tid & 15, ty = tid >> 4;
    int r0 = rt * 64, c0 = ct * 64;
    float acc[4][4] = {};
    for (int kc = 0; kc < PC; kc += 32) {
        #pragma unroll
        for (int l = 0; l < 8; l++) {
            int e = tid + l * 256;
            int row = e >> 5, col = e & 31;
            int rr = r0 + row;
            int bb = rr >> 10, nn = rr & 1023;
            int kkk = kc + col;
            int gg = kkk / 96, dd = kkk % 96;
            a_s[col][row] = g_oh[(((size_t)bb * 8 + gg) * PN + nn) * PD + dd];
            w_s[col][row] = pw[(size_t)(c0 + row) * PC + kkk];
        }
        __syncthreads();
        #pragma unroll
        for (int kk = 0; kk < 32; kk++) {
            float a[4], bb2[4];
            #pragma unroll
            for (int i2 = 0; i2 < 4; i2++) a[i2] = a_s[kk][ty * 4 + i2];
            #pragma unroll
            for (int j2 = 0; j2 < 4; j2++) bb2[j2] = w_s[kk][tx * 4 + j2];
            #pragma unroll
            for (int i2 = 0; i2 < 4; i2++)
                #pragma unroll
                for (int j2 = 0; j2 < 4; j2++) acc[i2][j2] += a[i2] * bb2[j2];
        }
        __syncthreads();
    }
    #pragma unroll
    for (int i2 = 0; i2 < 4; i2++)
        #pragma unroll
        for (int j2 = 0; j2 < 4; j2++)
            out[(size_t)(r0 + ty * 4 + i2) * PC + c0 + tx * 4 + j2] =
                acc[i2][j2] + pb[c0 + tx * 4 + j2];
}

// ---------------------------------------------------------------------------
extern "C" void kernel_launch(void* const* d_in, const int* in_sizes, int n_in,
                              void* d_out, int out_size) {
    const float* x  = (const float*)d_in[0];
    const float* wq = (const float*)d_in[1];
    const float* wk = (const float*)d_in[2];
    const float* wv = (const float*)d_in[3];
    const float* rw = (const float*)d_in[4];
    const float* rb = (const float*)d_in[5];
    const float* gm = (const float*)d_in[6];
    const float* bt = (const float*)d_in[7];
    const float* pw = (const float*)d_in[8];
    const float* pb = (const float*)d_in[9];
    float* out = (float*)d_out;
    float* attn_out = out + (size_t)PB * PN * PC;  // attn follows out in d_out

    zero_stats_kernel<<<1, 32>>>();
    conv_qkv_kernel<<<PB * PN, 256>>>(x, wq, wk, wv);
    qk_gemm_kernel<<<dim3(16, 16, 64), 256>>>();
    softmax_mix_kernel<<<PB * PN, 256>>>(rw, rb);
    finalize_kernel<<<1, 32>>>(gm, bt);
    bn_av_kernel<<<dim3(16, 64), 256>>>(attn_out);
    proj_kernel<<<dim3(12, 128), 256>>>(pw, pb, out);
}

// round 2
// speedup vs baseline: 1.5723x; 1.5723x over previous
#include <cuda_runtime.h>
#include <math.h>

#define PB 8
#define PN 1024
#define PC 768
#define PH 8
#define PD 96
#define PM 1024

__device__ float  g_q[(size_t)PB*PN*PC];
__device__ float  g_k[(size_t)PB*PN*PC];
__device__ float  g_v[(size_t)PB*PN*PC];
__device__ float  g_S[(size_t)PB*PH*PN*PM];   // scores, then mixed pre-BN attn (in place)
__device__ float  g_oh[(size_t)PB*PN*PC];     // attn_norm @ V, layout (b,g,n,d)
__device__ double g_stats[16];
__device__ float  g_norm[16];

// ---------------------------------------------------------------------------
__global__ void zero_stats_kernel() {
    if (threadIdx.x < 16) g_stats[threadIdx.x] = 0.0;
}

// ---------------------------------------------------------------------------
// Per-token 3x3 SAME convs (3->3 ch) on 3x16x16 images; one block per image.
__global__ void conv_qkv_kernel(const float* __restrict__ x,
                                const float* __restrict__ wq,
                                const float* __restrict__ wk,
                                const float* __restrict__ wv) {
    __shared__ float simg[3][16][16];
    __shared__ float sw[3][81];
    int img = blockIdx.x;
    int tid = threadIdx.x;
    for (int e = tid; e < 768; e += 256)
        ((float*)simg)[e] = x[(size_t)img * 768 + e];
    if (tid < 81) { sw[0][tid] = wq[tid]; sw[1][tid] = wk[tid]; sw[2][tid] = wv[tid]; }
    __syncthreads();
    int i = tid >> 4, j = tid & 15;
    float out[3][3];
    #pragma unroll
    for (int a = 0; a < 3; a++)
        #pragma unroll
        for (int c = 0; c < 3; c++) out[a][c] = 0.f;
    #pragma unroll
    for (int ci = 0; ci < 3; ci++)
        #pragma unroll
        for (int di = 0; di < 3; di++) {
            int ii = i + di - 1;
            if (ii < 0 || ii > 15) continue;
            #pragma unroll
            for (int dj = 0; dj < 3; dj++) {
                int jj = j + dj - 1;
                if (jj < 0 || jj > 15) continue;
                float pix = simg[ci][ii][jj];
                int wi = ci * 9 + di * 3 + dj;
                #pragma unroll
                for (int co = 0; co < 3; co++) {
                    out[0][co] += pix * sw[0][co * 27 + wi];
                    out[1][co] += pix * sw[1][co * 27 + wi];
                    out[2][co] += pix * sw[2][co * 27 + wi];
                }
            }
        }
    #pragma unroll
    for (int co = 0; co < 3; co++) {
        int c = co * 256 + i * 16 + j;
        size_t o = (size_t)img * 768 + c;
        g_q[o] = out[0][co];
        g_k[o] = out[1][co];
        g_v[o] = out[2][co];
    }
}

// ---------------------------------------------------------------------------
// S[b,h,n,m] = scale * q[b,n,h,:] . k[b,m,h,:]
// 128x128 tile, K-chunk 32, 8x8 micro-tile per thread.
__global__ void __launch_bounds__(256, 2) qk_gemm_kernel() {
    __shared__ float a_s[32][132];
    __shared__ float b_s[32][132];
    int mt = blockIdx.x, nt = blockIdx.y, bh = blockIdx.z;
    int b = bh >> 3, h = bh & 7;
    int tid = threadIdx.x;
    int tx = tid & 15, ty = tid >> 4;
    const float* qb = g_q + (size_t)b * PN * PC + h * PD;
    const float* kb = g_k + (size_t)b * PN * PC + h * PD;
    int n0 = nt * 128, m0 = mt * 128;
    int lrow = tid >> 3, lc4 = (tid & 7) * 4;
    float acc[8][8] = {};
    for (int kc = 0; kc < PD; kc += 32) {
        #pragma unroll
        for (int p = 0; p < 4; p++) {
            int row = lrow + p * 32;
            float4 fa = *(const float4*)&qb[(size_t)(n0 + row) * PC + kc + lc4];
            float4 fb = *(const float4*)&kb[(size_t)(m0 + row) * PC + kc + lc4];
            a_s[lc4 + 0][row] = fa.x; a_s[lc4 + 1][row] = fa.y;
            a_s[lc4 + 2][row] = fa.z; a_s[lc4 + 3][row] = fa.w;
            b_s[lc4 + 0][row] = fb.x; b_s[lc4 + 1][row] = fb.y;
            b_s[lc4 + 2][row] = fb.z; b_s[lc4 + 3][row] = fb.w;
        }
        __syncthreads();
        #pragma unroll
        for (int kk = 0; kk < 32; kk++) {
            float4 a0 = *(const float4*)&a_s[kk][ty * 8];
            float4 a1 = *(const float4*)&a_s[kk][ty * 8 + 4];
            float4 b0 = *(const float4*)&b_s[kk][tx * 8];
            float4 b1 = *(const float4*)&b_s[kk][tx * 8 + 4];
            float av[8] = {a0.x, a0.y, a0.z, a0.w, a1.x, a1.y, a1.z, a1.w};
            float bv[8] = {b0.x, b0.y, b0.z, b0.w, b1.x, b1.y, b1.z, b1.w};
            #pragma unroll
            for (int i2 = 0; i2 < 8; i2++)
                #pragma unroll
                for (int j2 = 0; j2 < 8; j2++) acc[i2][j2] += av[i2] * bv[j2];
        }
        __syncthreads();
    }
    const float scale = 0.10206207261596577f;  // 96^-0.5
    float* Sb = g_S + ((size_t)bh * PN + n0) * PM + m0;
    #pragma unroll
    for (int i2 = 0; i2 < 8; i2++) {
        float4 o0, o1;
        o0.x = acc[i2][0] * scale; o0.y = acc[i2][1] * scale;
        o0.z = acc[i2][2] * scale; o0.w = acc[i2][3] * scale;
        o1.x = acc[i2][4] * scale; o1.y = acc[i2][5] * scale;
        o1.z = acc[i2][6] * scale; o1.w = acc[i2][7] * scale;
        *(float4*)&Sb[(size_t)(ty * 8 + i2) * PM + tx * 8] = o0;
        *(float4*)&Sb[(size_t)(ty * 8 + i2) * PM + tx * 8 + 4] = o1;
    }
}

// ---------------------------------------------------------------------------
// One block per (b,n): register-resident softmax over m for all 8 heads,
// head-mix (8x8)+bias, write mixed pre-BN attn back to g_S in place,
// accumulate BN stats.
__global__ void __launch_bounds__(256) softmax_mix_kernel(const float* __restrict__ rw,
                                                          const float* __restrict__ rb) {
    __shared__ float red[8][8];
    __shared__ float smax[8];
    __shared__ float sinv[8];
    __shared__ float wsc[8][8];
    __shared__ float sbias[8];
    __shared__ float ssum[8], ssq[8];
    int bn = blockIdx.x;
    int b = bn >> 10, n = bn & 1023;
    int tid = threadIdx.x;
    int lane = tid & 31, warp = tid >> 5;
    if (tid < 8) { sbias[tid] = rb[tid]; ssum[tid] = 0.f; ssq[tid] = 0.f; }

    float4 r[8];
    #pragma unroll
    for (int h = 0; h < 8; h++)
        r[h] = *(const float4*)&g_S[(((size_t)(b * 8 + h)) * PN + n) * PM + tid * 4];

    // per-head max (all 8 heads reduced together)
    float mx[8];
    #pragma unroll
    for (int h = 0; h < 8; h++) {
        mx[h] = fmaxf(fmaxf(r[h].x, r[h].y), fmaxf(r[h].z, r[h].w));
        #pragma unroll
        for (int off = 16; off; off >>= 1)
            mx[h] = fmaxf(mx[h], __shfl_xor_sync(0xffffffffu, mx[h], off));
    }
    if (lane == 0)
        #pragma unroll
        for (int h = 0; h < 8; h++) red[warp][h] = mx[h];
    __syncthreads();
    if (tid < 8) {
        float m2 = red[0][tid];
        #pragma unroll
        for (int w = 1; w < 8; w++) m2 = fmaxf(m2, red[w][tid]);
        smax[tid] = m2;
    }
    __syncthreads();

    // exp + per-head sum
    float sm[8];
    #pragma unroll
    for (int h = 0; h < 8; h++) {
        float m2 = smax[h];
        r[h].x = __expf(r[h].x - m2);
        r[h].y = __expf(r[h].y - m2);
        r[h].z = __expf(r[h].z - m2);
        r[h].w = __expf(r[h].w - m2);
        sm[h] = r[h].x + r[h].y + r[h].z + r[h].w;
        #pragma unroll
        for (int off = 16; off; off >>= 1)
            sm[h] += __shfl_xor_sync(0xffffffffu, sm[h], off);
    }
    if (lane == 0)
        #pragma unroll
        for (int h = 0; h < 8; h++) red[warp][h] = sm[h];
    __syncthreads();
    if (tid < 8) {
        float t = 0.f;
        #pragma unroll
        for (int w = 0; w < 8; w++) t += red[w][tid];
        sinv[tid] = 1.f / t;
    }
    __syncthreads();
    if (tid < 64) wsc[tid >> 3][tid & 7] = rw[tid] * sinv[tid & 7];
    __syncthreads();

    // mix + write + stats
    float ls[8], lq[8];
    #pragma unroll
    for (int g = 0; g < 8; g++) {
        float4 o;
        o.x = sbias[g]; o.y = sbias[g]; o.z = sbias[g]; o.w = sbias[g];
        #pragma unroll
        for (int h = 0; h < 8; h++) {
            float w = wsc[g][h];
            o.x += w * r[h].x; o.y += w * r[h].y;
            o.z += w * r[h].z; o.w += w * r[h].w;
        }
        *(float4*)&g_S[(((size_t)(b * 8 + g)) * PN + n) * PM + tid * 4] = o;
        ls[g] = o.x + o.y + o.z + o.w;
        lq[g] = o.x * o.x + o.y * o.y + o.z * o.z + o.w * o.w;
    }
    #pragma unroll
    for (int g = 0; g < 8; g++) {
        #pragma unroll
        for (int off = 16; off; off >>= 1) {
            ls[g] += __shfl_xor_sync(0xffffffffu, ls[g], off);
            lq[g] += __shfl_xor_sync(0xffffffffu, lq[g], off);
        }
        if (lane == 0) { atomicAdd(&ssum[g], ls[g]); atomicAdd(&ssq[g], lq[g]); }
    }
    __syncthreads();
    if (tid < 8) {
        atomicAdd(&g_stats[tid], (double)ssum[tid]);
        atomicAdd(&g_stats[8 + tid], (double)ssq[tid]);
    }
}

// ---------------------------------------------------------------------------
__global__ void finalize_kernel(const float* __restrict__ gamma,
                                const float* __restrict__ beta) {
    int g = threadIdx.x;
    if (g < 8) {
        double cnt = 8388608.0;  // B*N*M
        double mean = g_stats[g] / cnt;
        double var = g_stats[8 + g] / cnt - mean * mean;
        double invstd = rsqrt(var + 1e-5);
        double A = invstd * (double)gamma[g];
        g_norm[g] = (float)A;
        g_norm[8 + g] = (float)((double)beta[g] - mean * A);
    }
}

// ---------------------------------------------------------------------------
// BN normalize-on-load + attn@V. Tile 128n x 96d per (nt, bg), m-chunk 32,
// 8x6 micro-tile. Writes normalized attn to d_out region, out to g_oh.
__global__ void __launch_bounds__(256, 2) bn_av_kernel(float* __restrict__ attn_out) {
    __shared__ float a_s[32][132];
    __shared__ float v_s[32][96];
    int nt = blockIdx.x, bg = blockIdx.y;
    int b = bg >> 3, g = bg & 7;
    int tid = threadIdx.x, tx = tid & 15, ty = tid >> 4;
    float A = g_norm[g], Bc = g_norm[8 + g];
    const float* Sb = g_S + (size_t)bg * PN * PM;
    float* aoB = attn_out + (size_t)bg * PN * PM;
    const float* vB = g_v + (size_t)b * PN * PC + g * PD;
    int n0 = nt * 128;
    int lrow = tid >> 3, lc4 = (tid & 7) * 4;
    float acc[8][6] = {};
    for (int m0 = 0; m0 < PM; m0 += 32) {
        #pragma unroll
        for (int p = 0; p < 4; p++) {
            int row = lrow + p * 32;
            size_t gi = (size_t)(n0 + row) * PM + m0 + lc4;
            float4 s = *(const float4*)&Sb[gi];
            s.x = s.x * A + Bc; s.y = s.y * A + Bc;
            s.z = s.z * A + Bc; s.w = s.w * A + Bc;
            *(float4*)&aoB[gi] = s;
            a_s[lc4 + 0][row] = s.x; a_s[lc4 + 1][row] = s.y;
            a_s[lc4 + 2][row] = s.z; a_s[lc4 + 3][row] = s.w;
        }
        #pragma unroll
        for (int p = 0; p < 3; p++) {
            int f4 = tid + p * 256;
            int mr = f4 / 24, c4 = (f4 % 24) * 4;
            float4 v = *(const float4*)&vB[(size_t)(m0 + mr) * PC + c4];
            *(float4*)&v_s[mr][c4] = v;
        }
        __syncthreads();
        #pragma unroll
        for (int kk = 0; kk < 32; kk++) {
            float4 a0 = *(const float4*)&a_s[kk][ty * 8];
            float4 a1 = *(const float4*)&a_s[kk][ty * 8 + 4];
            float av[8] = {a0.x, a0.y, a0.z, a0.w, a1.x, a1.y, a1.z, a1.w};
            float2 v0 = *(const float2*)&v_s[kk][tx * 6];
            float2 v1 = *(const float2*)&v_s[kk][tx * 6 + 2];
            float2 v2 = *(const float2*)&v_s[kk][tx * 6 + 4];
            float vv[6] = {v0.x, v0.y, v1.x, v1.y, v2.x, v2.y};
            #pragma unroll
            for (int i2 = 0; i2 < 8; i2++)
                #pragma unroll
                for (int j2 = 0; j2 < 6; j2++) acc[i2][j2] += av[i2] * vv[j2];
        }
        __syncthreads();
    }
    float* ohB = g_oh + ((size_t)bg * PN + n0) * PD;
    #pragma unroll
    for (int i2 = 0; i2 < 8; i2++) {
        float2 o0 = {acc[i2][0], acc[i2][1]};
        float2 o1 = {acc[i2][2], acc[i2][3]};
        float2 o2 = {acc[i2][4], acc[i2][5]};
        *(float2*)&ohB[(size_t)(ty * 8 + i2) * PD + tx * 6] = o0;
        *(float2*)&ohB[(size_t)(ty * 8 + i2) * PD + tx * 6 + 2] = o1;
        *(float2*)&ohB[(size_t)(ty * 8 + i2) * PD + tx * 6 + 4] = o2;
    }
}

// ---------------------------------------------------------------------------
// out[r,c] = sum_k oh[b, k/96, n, k%96] * pw[c,k] + pb[c]; 128x128 tiles.
__global__ void __launch_bounds__(256, 2) proj_kernel(const float* __restrict__ pw,
                                                      const float* __restrict__ pb,
                                                      float* __restrict__ out) {
    __shared__ float a_s[32][132];
    __shared__ float w_s[32][132];
    int ct = blockIdx.x, rt = blockIdx.y;
    int tid = threadIdx.x, tx = tid & 15, ty = tid >> 4;
    int r0 = rt * 128, c0 = ct * 128;
    int lrow = tid >> 3, lc4 = (tid & 7) * 4;
    float acc[8][8] = {};
    for (int kc = 0; kc < PC; kc += 32) {
        int gg = kc / 96;
        int dd0 = kc - gg * 96;
        #pragma unroll
        for (int p = 0; p < 4; p++) {
            int row = lrow + p * 32;
            int rr = r0 + row;
            int bb = rr >> 10, nn = rr & 1023;
            float4 fa = *(const float4*)&g_oh[(((size_t)bb * 8 + gg) * PN + nn) * PD + dd0 + lc4];
            float4 fw = *(const float4*)&pw[(size_t)(c0 + row) * PC + kc + lc4];
            a_s[lc4 + 0][row] = fa.x; a_s[lc4 + 1][row] = fa.y;
            a_s[lc4 + 2][row] = fa.z; a_s[lc4 + 3][row] = fa.w;
            w_s[lc4 + 0][row] = fw.x; w_s[lc4 + 1][row] = fw.y;
            w_s[lc4 + 2][row] = fw.z; w_s[lc4 + 3][row] = fw.w;
        }
        __syncthreads();
        #pragma unroll
        for (int kk = 0; kk < 32; kk++) {
            float4 a0 = *(const float4*)&a_s[kk][ty * 8];
            float4 a1 = *(const float4*)&a_s[kk][ty * 8 + 4];
            float4 b0 = *(const float4*)&w_s[kk][tx * 8];
            float4 b1 = *(const float4*)&w_s[kk][tx * 8 + 4];
            float av[8] = {a0.x, a0.y, a0.z, a0.w, a1.x, a1.y, a1.z, a1.w};
            float bv[8] = {b0.x, b0.y, b0.z, b0.w, b1.x, b1.y, b1.z, b1.w};
            #pragma unroll
            for (int i2 = 0; i2 < 8; i2++)
                #pragma unroll
                for (int j2 = 0; j2 < 8; j2++) acc[i2][j2] += av[i2] * bv[j2];
        }
        __syncthreads();
    }
    #pragma unroll
    for (int i2 = 0; i2 < 8; i2++) {
        float4 o0, o1;
        int cc = c0 + tx * 8;
        o0.x = acc[i2][0] + pb[cc + 0]; o0.y = acc[i2][1] + pb[cc + 1];
        o0.z = acc[i2][2] + pb[cc + 2]; o0.w = acc[i2][3] + pb[cc + 3];
        o1.x = acc[i2][4] + pb[cc + 4]; o1.y = acc[i2][5] + pb[cc + 5];
        o1.z = acc[i2][6] + pb[cc + 6]; o1.w = acc[i2][7] + pb[cc + 7];
        *(float4*)&out[(size_t)(r0 + ty * 8 + i2) * PC + cc] = o0;
        *(float4*)&out[(size_t)(r0 + ty * 8 + i2) * PC + cc + 4] = o1;
    }
}

// ---------------------------------------------------------------------------
extern "C" void kernel_launch(void* const* d_in, const int* in_sizes, int n_in,
                              void* d_out, int out_size) {
    const float* x  = (const float*)d_in[0];
    const float* wq = (const float*)d_in[1];
    const float* wk = (const float*)d_in[2];
    const float* wv = (const float*)d_in[3];
    const float* rw = (const float*)d_in[4];
    const float* rb = (const float*)d_in[5];
    const float* gm = (const float*)d_in[6];
    const float* bt = (const float*)d_in[7];
    const float* pw = (const float*)d_in[8];
    const float* pb = (const float*)d_in[9];
    float* out = (float*)d_out;
    float* attn_out = out + (size_t)PB * PN * PC;

    zero_stats_kernel<<<1, 32>>>();
    conv_qkv_kernel<<<PB * PN, 256>>>(x, wq, wk, wv);
    qk_gemm_kernel<<<dim3(8, 8, 64), 256>>>();
    softmax_mix_kernel<<<PB * PN, 256>>>(rw, rb);
    finalize_kernel<<<1, 32>>>(gm, bt);
    bn_av_kernel<<<dim3(8, 64), 256>>>(attn_out);
    proj_kernel<<<dim3(6, 64), 256>>>(pw, pb, out);
}

// round 5
// speedup vs baseline: 1.7625x; 1.1210x over previous
#include <cuda_runtime.h>
#include <cuda_bf16.h>
#include <math.h>
#include <cstdint>

#define PB 8
#define PN 1024
#define PC 768
#define PH 8
#define PD 96
#define PM 1024

__device__ float  g_q[(size_t)PB*PN*PC];
__device__ float  g_k[(size_t)PB*PN*PC];
__device__ float  g_v[(size_t)PB*PN*PC];
__device__ float  g_S[(size_t)PB*PH*PN*PM];   // scores, then mixed pre-BN attn (in place)
__device__ float  g_oh[(size_t)PB*PN*PC];     // attn_norm @ V, layout (b,g,n,d)
__device__ double g_stats[16];
__device__ float  g_norm[16];

// ============================ helpers ======================================
__device__ __forceinline__ uint32_t smem_u32(const void* p) {
    uint32_t a;
    asm("{ .reg .u64 t; cvta.to.shared.u64 t, %1; cvt.u32.u64 %0, t; }"
        : "=r"(a) : "l"(p));
    return a;
}

__device__ __forceinline__ void ldsm4(uint32_t addr, uint32_t* r) {
    asm volatile("ldmatrix.sync.aligned.m8n8.x4.shared.b16 {%0,%1,%2,%3}, [%4];"
                 : "=r"(r[0]), "=r"(r[1]), "=r"(r[2]), "=r"(r[3]) : "r"(addr));
}

__device__ __forceinline__ void mma16816(float* d, const uint32_t* a, const uint32_t* b) {
    asm volatile("mma.sync.aligned.m16n8k16.row.col.f32.bf16.bf16.f32 "
                 "{%0,%1,%2,%3}, {%4,%5,%6,%7}, {%8,%9}, {%0,%1,%2,%3};"
                 : "+f"(d[0]), "+f"(d[1]), "+f"(d[2]), "+f"(d[3])
                 : "r"(a[0]), "r"(a[1]), "r"(a[2]), "r"(a[3]), "r"(b[0]), "r"(b[1]));
}

// hi/lo bf16 split of two floats, packed
__device__ __forceinline__ void split2(float x, float y, uint32_t& hi, uint32_t& lo) {
    __nv_bfloat16 hx = __float2bfloat16_rn(x), hy = __float2bfloat16_rn(y);
    __nv_bfloat16 lx = __float2bfloat16_rn(x - __bfloat162float(hx));
    __nv_bfloat16 ly = __float2bfloat16_rn(y - __bfloat162float(hy));
    hi = (uint32_t)__bfloat16_as_ushort(hx) | ((uint32_t)__bfloat16_as_ushort(hy) << 16);
    lo = (uint32_t)__bfloat16_as_ushort(lx) | ((uint32_t)__bfloat16_as_ushort(ly) << 16);
}

// store 4 consecutive k-cols of one row into padded hi/lo bf16 tiles
__device__ __forceinline__ void split_store4(char* hi, char* lo, int row, int c4,
                                             int stride, float4 f) {
    uint32_t h0, l0, h1, l1;
    split2(f.x, f.y, h0, l0);
    split2(f.z, f.w, h1, l1);
    uint32_t off = (uint32_t)(row * stride + c4) * 2;
    *(uint2*)(hi + off) = make_uint2(h0, h1);
    *(uint2*)(lo + off) = make_uint2(l0, l1);
}

__device__ __forceinline__ void store_h(char* b, int row, int col, int stride,
                                        __nv_bfloat16 v) {
    *(__nv_bfloat16*)(b + (uint32_t)(row * stride + col) * 2) = v;
}

// ---------------------------------------------------------------------------
__global__ void zero_stats_kernel() {
    if (threadIdx.x < 16) g_stats[threadIdx.x] = 0.0;
}

// ---------------------------------------------------------------------------
// Per-token 3x3 SAME convs (3->3 ch) on 3x16x16 images; one block per image.
__global__ void conv_qkv_kernel(const float* __restrict__ x,
                                const float* __restrict__ wq,
                                const float* __restrict__ wk,
                                const float* __restrict__ wv) {
    __shared__ float simg[3][16][16];
    __shared__ float sw[3][81];
    int img = blockIdx.x;
    int tid = threadIdx.x;
    for (int e = tid; e < 768; e += 256)
        ((float*)simg)[e] = x[(size_t)img * 768 + e];
    if (tid < 81) { sw[0][tid] = wq[tid]; sw[1][tid] = wk[tid]; sw[2][tid] = wv[tid]; }
    __syncthreads();
    int i = tid >> 4, j = tid & 15;
    float out[3][3];
    #pragma unroll
    for (int a = 0; a < 3; a++)
        #pragma unroll
        for (int c = 0; c < 3; c++) out[a][c] = 0.f;
    #pragma unroll
    for (int ci = 0; ci < 3; ci++)
        #pragma unroll
        for (int di = 0; di < 3; di++) {
            int ii = i + di - 1;
            if (ii < 0 || ii > 15) continue;
            #pragma unroll
            for (int dj = 0; dj < 3; dj++) {
                int jj = j + dj - 1;
                if (jj < 0 || jj > 15) continue;
                float pix = simg[ci][ii][jj];
                int wi = ci * 9 + di * 3 + dj;
                #pragma unroll
                for (int co = 0; co < 3; co++) {
                    out[0][co] += pix * sw[0][co * 27 + wi];
                    out[1][co] += pix * sw[1][co * 27 + wi];
                    out[2][co] += pix * sw[2][co * 27 + wi];
                }
            }
        }
    #pragma unroll
    for (int co = 0; co < 3; co++) {
        int c = co * 256 + i * 16 + j;
        size_t o = (size_t)img * 768 + c;
        g_q[o] = out[0][co];
        g_k[o] = out[1][co];
        g_v[o] = out[2][co];
    }
}

// ===========================================================================
// qk: S[bh][n][m] = scale*q.k via mma.sync bf16 3-term split.
// Block tile 128(n) x 128(m), K=96. 8 warps: 4(row)x2(col), warp tile 32x64.
// ===========================================================================
#define QK_SA 104                         // halves per row (96 + 8 pad)
#define QK_TILE (128 * QK_SA * 2)         // 26624 B
#define QK_SMEM (4 * QK_TILE)

__global__ void __launch_bounds__(256) qk_mma_kernel() {
    extern __shared__ char smem[];
    char* AHI = smem;
    char* ALO = smem + QK_TILE;
    char* BHI = smem + 2 * QK_TILE;
    char* BLO = smem + 3 * QK_TILE;
    int tid = threadIdx.x, wid = tid >> 5, lane = tid & 31;
    int mt = blockIdx.x, nt = blockIdx.y, bh = blockIdx.z;
    int b = bh >> 3, h = bh & 7;

    const float* qb = g_q + (size_t)b * PN * PC + h * PD;
    const float* kb = g_k + (size_t)b * PN * PC + h * PD;
    int n0 = nt * 128, m0 = mt * 128;
    const float scale = 0.10206207261596577f;

    #pragma unroll
    for (int i = 0; i < 12; i++) {
        int idx = tid + i * 256;
        int row = idx / 24, c4 = (idx % 24) * 4;
        float4 f = *(const float4*)&qb[(size_t)(n0 + row) * PC + c4];
        f.x *= scale; f.y *= scale; f.z *= scale; f.w *= scale;
        split_store4(AHI, ALO, row, c4, QK_SA, f);
        float4 g = *(const float4*)&kb[(size_t)(m0 + row) * PC + c4];
        split_store4(BHI, BLO, row, c4, QK_SA, g);
    }
    __syncthreads();

    uint32_t uAHI = smem_u32(AHI), uALO = smem_u32(ALO);
    uint32_t uBHI = smem_u32(BHI), uBLO = smem_u32(BLO);
    int lr = lane & 7;
    int a_row = lr + ((lane >> 3) & 1) * 8, a_k = (lane >> 4) * 8;
    int b_row = lr + (lane >> 4) * 8,       b_k = ((lane >> 3) & 1) * 8;
    int wr = (wid >> 1) * 32, wc = (wid & 1) * 64;

    float acc[2][8][4] = {};
    #pragma unroll
    for (int ks = 0; ks < 6; ks++) {
        int k0 = ks * 16;
        uint32_t ah[2][4], al[2][4];
        #pragma unroll
        for (int mf = 0; mf < 2; mf++) {
            uint32_t off = (uint32_t)((wr + mf * 16 + a_row) * QK_SA + k0 + a_k) * 2;
            ldsm4(uAHI + off, ah[mf]);
            ldsm4(uALO + off, al[mf]);
        }
        #pragma unroll
        for (int np = 0; np < 4; np++) {
            uint32_t off = (uint32_t)((wc + np * 16 + b_row) * QK_SA + k0 + b_k) * 2;
            uint32_t bh4[4], bl4[4];
            ldsm4(uBHI + off, bh4);
            ldsm4(uBLO + off, bl4);
            #pragma unroll
            for (int mf = 0; mf < 2; mf++)
                #pragma unroll
                for (int sub = 0; sub < 2; sub++) {
                    float* d = acc[mf][np * 2 + sub];
                    mma16816(d, ah[mf], &bh4[sub * 2]);
                    mma16816(d, ah[mf], &bl4[sub * 2]);
                    mma16816(d, al[mf], &bh4[sub * 2]);
                }
        }
    }

    float* Sb = g_S + ((size_t)bh * PN + n0) * PM + m0;
    int r0 = wr + (lane >> 2);
    int cbase = wc + 2 * (lane & 3);
    #pragma unroll
    for (int mf = 0; mf < 2; mf++)
        #pragma unroll
        for (int nf = 0; nf < 8; nf++) {
            int rr = r0 + mf * 16, cc = cbase + nf * 8;
            *(float2*)&Sb[(size_t)rr * PM + cc]       = make_float2(acc[mf][nf][0], acc[mf][nf][1]);
            *(float2*)&Sb[(size_t)(rr + 8) * PM + cc] = make_float2(acc[mf][nf][2], acc[mf][nf][3]);
        }
}

// ---------------------------------------------------------------------------
// Register-resident softmax + head-mix + BN stats
__global__ void __launch_bounds__(256) softmax_mix_kernel(const float* __restrict__ rw,
                                                          const float* __restrict__ rb) {
    __shared__ float red[8][8];
    __shared__ float smax[8];
    __shared__ float sinv[8];
    __shared__ float wsc[8][8];
    __shared__ float sbias[8];
    __shared__ float ssum[8], ssq[8];
    int bn = blockIdx.x;
    int b = bn >> 10, n = bn & 1023;
    int tid = threadIdx.x;
    int lane = tid & 31, warp = tid >> 5;
    if (tid < 8) { sbias[tid] = rb[tid]; ssum[tid] = 0.f; ssq[tid] = 0.f; }

    float4 r[8];
    #pragma unroll
    for (int h = 0; h < 8; h++)
        r[h] = *(const float4*)&g_S[(((size_t)(b * 8 + h)) * PN + n) * PM + tid * 4];

    float mx[8];
    #pragma unroll
    for (int h = 0; h < 8; h++) {
        mx[h] = fmaxf(fmaxf(r[h].x, r[h].y), fmaxf(r[h].z, r[h].w));
        #pragma unroll
        for (int off = 16; off; off >>= 1)
            mx[h] = fmaxf(mx[h], __shfl_xor_sync(0xffffffffu, mx[h], off));
    }
    if (lane == 0)
        #pragma unroll
        for (int h = 0; h < 8; h++) red[warp][h] = mx[h];
    __syncthreads();
    if (tid < 8) {
        float m2 = red[0][tid];
        #pragma unroll
        for (int w = 1; w < 8; w++) m2 = fmaxf(m2, red[w][tid]);
        smax[tid] = m2;
    }
    __syncthreads();

    float sm[8];
    #pragma unroll
    for (int h = 0; h < 8; h++) {
        float m2 = smax[h];
        r[h].x = __expf(r[h].x - m2);
        r[h].y = __expf(r[h].y - m2);
        r[h].z = __expf(r[h].z - m2);
        r[h].w = __expf(r[h].w - m2);
        sm[h] = r[h].x + r[h].y + r[h].z + r[h].w;
        #pragma unroll
        for (int off = 16; off; off >>= 1)
            sm[h] += __shfl_xor_sync(0xffffffffu, sm[h], off);
    }
    if (lane == 0)
        #pragma unroll
        for (int h = 0; h < 8; h++) red[warp][h] = sm[h];
    __syncthreads();
    if (tid < 8) {
        float t = 0.f;
        #pragma unroll
        for (int w = 0; w < 8; w++) t += red[w][tid];
        sinv[tid] = 1.f / t;
    }
    __syncthreads();
    if (tid < 64) wsc[tid >> 3][tid & 7] = rw[tid] * sinv[tid & 7];
    __syncthreads();

    float ls[8], lq[8];
    #pragma unroll
    for (int g = 0; g < 8; g++) {
        float4 o;
        o.x = sbias[g]; o.y = sbias[g]; o.z = sbias[g]; o.w = sbias[g];
        #pragma unroll
        for (int h = 0; h < 8; h++) {
            float w = wsc[g][h];
            o.x += w * r[h].x; o.y += w * r[h].y;
            o.z += w * r[h].z; o.w += w * r[h].w;
        }
        *(float4*)&g_S[(((size_t)(b * 8 + g)) * PN + n) * PM + tid * 4] = o;
        ls[g] = o.x + o.y + o.z + o.w;
        lq[g] = o.x * o.x + o.y * o.y + o.z * o.z + o.w * o.w;
    }
    #pragma unroll
    for (int g = 0; g < 8; g++) {
        #pragma unroll
        for (int off = 16; off; off >>= 1) {
            ls[g] += __shfl_xor_sync(0xffffffffu, ls[g], off);
            lq[g] += __shfl_xor_sync(0xffffffffu, lq[g], off);
        }
        if (lane == 0) { atomicAdd(&ssum[g], ls[g]); atomicAdd(&ssq[g], lq[g]); }
    }
    __syncthreads();
    if (tid < 8) {
        atomicAdd(&g_stats[tid], (double)ssum[tid]);
        atomicAdd(&g_stats[8 + tid], (double)ssq[tid]);
    }
}

// ---------------------------------------------------------------------------
__global__ void finalize_kernel(const float* __restrict__ gamma,
                                const float* __restrict__ beta) {
    int g = threadIdx.x;
    if (g < 8) {
        double cnt = 8388608.0;
        double mean = g_stats[g] / cnt;
        double var = g_stats[8 + g] / cnt - mean * mean;
        double invstd = rsqrt(var + 1e-5);
        double A = invstd * (double)gamma[g];
        g_norm[g] = (float)A;
        g_norm[8 + g] = (float)((double)beta[g] - mean * A);
    }
}

// ===========================================================================
// av: BN normalize-on-load + attn@V. Block tile 128(n) x 96(d), K=1024 (m)
// in 8 chunks of 128. B = V^T staged transposed. 8 warps 4x2, warp 32x48.
// ===========================================================================
#define AV_SA 136
#define AV_ATILE (128 * AV_SA * 2)        // 34816
#define AV_BTILE (96 * AV_SA * 2)         // 26112
#define AV_SMEM (2 * AV_ATILE + 2 * AV_BTILE)

__global__ void __launch_bounds__(256) av_mma_kernel(float* __restrict__ attn_out) {
    extern __shared__ char smem[];
    char* AHI = smem;
    char* ALO = smem + AV_ATILE;
    char* BHI = smem + 2 * AV_ATILE;
    char* BLO = smem + 2 * AV_ATILE + AV_BTILE;
    int tid = threadIdx.x, wid = tid >> 5, lane = tid & 31;
    int nt = blockIdx.x, bg = blockIdx.y;
    int b = bg >> 3, g = bg & 7;

    float A = g_norm[g], Bc = g_norm[8 + g];
    const float* Sb = g_S + (size_t)bg * PN * PM;
    float* aoB = attn_out + (size_t)bg * PN * PM;
    const float* vB = g_v + (size_t)b * PN * PC + g * PD;
    int n0 = nt * 128;

    uint32_t uAHI = smem_u32(AHI), uALO = smem_u32(ALO);
    uint32_t uBHI = smem_u32(BHI), uBLO = smem_u32(BLO);
    int lr = lane & 7;
    int a_row = lr + ((lane >> 3) & 1) * 8, a_k = (lane >> 4) * 8;
    int b_row = lr + (lane >> 4) * 8,       b_k = ((lane >> 3) & 1) * 8;
    int wr = (wid >> 1) * 32, wc = (wid & 1) * 48;

    float acc[2][6][4] = {};
    for (int ch = 0; ch < 8; ch++) {
        int m0 = ch * 128;
        // stage A: normalized attn (also to attn_out)
        #pragma unroll
        for (int i = 0; i < 16; i++) {
            int idx = tid + i * 256;
            int row = idx >> 5, c4 = (idx & 31) * 4;
            size_t gi = (size_t)(n0 + row) * PM + m0 + c4;
            float4 s = *(const float4*)&Sb[gi];
            s.x = s.x * A + Bc; s.y = s.y * A + Bc;
            s.z = s.z * A + Bc; s.w = s.w * A + Bc;
            *(float4*)&aoB[gi] = s;
            split_store4(AHI, ALO, row, c4, AV_SA, s);
        }
        // stage B: V^T (rows d 96, cols m 128)
        #pragma unroll
        for (int i = 0; i < 12; i++) {
            int idx = tid + i * 256;
            int mr = idx / 24, d4 = (idx % 24) * 4;
            float4 f = *(const float4*)&vB[(size_t)(m0 + mr) * PC + d4];
            float v4[4] = {f.x, f.y, f.z, f.w};
            #pragma unroll
            for (int j = 0; j < 4; j++) {
                __nv_bfloat16 hv = __float2bfloat16_rn(v4[j]);
                __nv_bfloat16 lv = __float2bfloat16_rn(v4[j] - __bfloat162float(hv));
                store_h(BHI, d4 + j, mr, AV_SA, hv);
                store_h(BLO, d4 + j, mr, AV_SA, lv);
            }
        }
        __syncthreads();

        #pragma unroll
        for (int ks = 0; ks < 8; ks++) {
            int k0 = ks * 16;
            uint32_t ah[2][4], al[2][4];
            #pragma unroll
            for (int mf = 0; mf < 2; mf++) {
                uint32_t off = (uint32_t)((wr + mf * 16 + a_row) * AV_SA + k0 + a_k) * 2;
                ldsm4(uAHI + off, ah[mf]);
                ldsm4(uALO + off, al[mf]);
            }
            #pragma unroll
            for (int np = 0; np < 3; np++) {
                uint32_t off = (uint32_t)((wc + np * 16 + b_row) * AV_SA + k0 + b_k) * 2;
                uint32_t bh4[4], bl4[4];
                ldsm4(uBHI + off, bh4);
                ldsm4(uBLO + off, bl4);
                #pragma unroll
                for (int mf = 0; mf < 2; mf++)
                    #pragma unroll
                    for (int sub = 0; sub < 2; sub++) {
                        float* d = acc[mf][np * 2 + sub];
                        mma16816(d, ah[mf], &bh4[sub * 2]);
                        mma16816(d, ah[mf], &bl4[sub * 2]);
                        mma16816(d, al[mf], &bh4[sub * 2]);
                    }
            }
        }
        __syncthreads();
    }

    float* ohB = g_oh + ((size_t)bg * PN + n0) * PD;
    int r0 = wr + (lane >> 2);
    int cbase = wc + 2 * (lane & 3);
    #pragma unroll
    for (int mf = 0; mf < 2; mf++)
        #pragma unroll
        for (int nf = 0; nf < 6; nf++) {
            int rr = r0 + mf * 16, cc = cbase + nf * 8;
            *(float2*)&ohB[(size_t)rr * PD + cc]       = make_float2(acc[mf][nf][0], acc[mf][nf][1]);
            *(float2*)&ohB[(size_t)(rr + 8) * PD + cc] = make_float2(acc[mf][nf][2], acc[mf][nf][3]);
        }
}

// ===========================================================================
// proj: out[r][c] = oh_flat[r][:] . pw[c][:] + pb[c]. 128x128 tiles, K=768
// in 6 chunks of 128.
// ===========================================================================
#define PJ_SA 136
#define PJ_TILE (128 * PJ_SA * 2)         // 34816
#define PJ_SMEM (4 * PJ_TILE)

__global__ void __launch_bounds__(256) proj_mma_kernel(const float* __restrict__ pw,
                                                       const float* __restrict__ pb,
                                                       float* __restrict__ out) {
    extern __shared__ char smem[];
    char* AHI = smem;
    char* ALO = smem + PJ_TILE;
    char* BHI = smem + 2 * PJ_TILE;
    char* BLO = smem + 3 * PJ_TILE;
    int tid = threadIdx.x, wid = tid >> 5, lane = tid & 31;
    int ct = blockIdx.x, rt = blockIdx.y;
    int r0b = rt * 128, c0 = ct * 128;

    uint32_t uAHI = smem_u32(AHI), uALO = smem_u32(ALO);
    uint32_t uBHI = smem_u32(BHI), uBLO = smem_u32(BLO);
    int lr = lane & 7;
    int a_row = lr + ((lane >> 3) & 1) * 8, a_k = (lane >> 4) * 8;
    int b_row = lr + (lane >> 4) * 8,       b_k = ((lane >> 3) & 1) * 8;
    int wr = (wid >> 1) * 32, wc = (wid & 1) * 64;

    float acc[2][8][4] = {};
    for (int ch = 0; ch < 6; ch++) {
        int kc = ch * 128;
        #pragma unroll
        for (int i = 0; i < 16; i++) {
            int idx = tid + i * 256;
            int row = idx >> 5, c4 = (idx & 31) * 4;
            int rr = r0b + row;
            int bb = rr >> 10, nn = rr & 1023;
            int k = kc + c4;
            int gg = k / 96, dd = k - gg * 96;
            float4 fa = *(const float4*)&g_oh[(((size_t)bb * 8 + gg) * PN + nn) * PD + dd];
            split_store4(AHI, ALO, row, c4, PJ_SA, fa);
            float4 fw = *(const float4*)&pw[(size_t)(c0 + row) * PC + k];
            split_store4(BHI, BLO, row, c4, PJ_SA, fw);
        }
        __syncthreads();

        #pragma unroll
        for (int ks = 0; ks < 8; ks++) {
            int k0 = ks * 16;
            uint32_t ah[2][4], al[2][4];
            #pragma unroll
            for (int mf = 0; mf < 2; mf++) {
                uint32_t off = (uint32_t)((wr + mf * 16 + a_row) * PJ_SA + k0 + a_k) * 2;
                ldsm4(uAHI + off, ah[mf]);
                ldsm4(uALO + off, al[mf]);
            }
            #pragma unroll
            for (int np = 0; np < 4; np++) {
                uint32_t off = (uint32_t)((wc + np * 16 + b_row) * PJ_SA + k0 + b_k) * 2;
                uint32_t bh4[4], bl4[4];
                ldsm4(uBHI + off, bh4);
                ldsm4(uBLO + off, bl4);
                #pragma unroll
                for (int mf = 0; mf < 2; mf++)
                    #pragma unroll
                    for (int sub = 0; sub < 2; sub++) {
                        float* d = acc[mf][np * 2 + sub];
                        mma16816(d, ah[mf], &bh4[sub * 2]);
                        mma16816(d, ah[mf], &bl4[sub * 2]);
                        mma16816(d, al[mf], &bh4[sub * 2]);
                    }
            }
        }
        __syncthreads();
    }

    int r0 = wr + (lane >> 2);
    int cbase = wc + 2 * (lane & 3);
    #pragma unroll
    for (int mf = 0; mf < 2; mf++)
        #pragma unroll
        for (int nf = 0; nf < 8; nf++) {
            int rr = r0b + r0 + mf * 16, cc = c0 + cbase + nf * 8;
            float2 o0 = make_float2(acc[mf][nf][0] + pb[cc], acc[mf][nf][1] + pb[cc + 1]);
            float2 o1 = make_float2(acc[mf][nf][2] + pb[cc], acc[mf][nf][3] + pb[cc + 1]);
            *(float2*)&out[(size_t)rr * PC + cc] = o0;
            *(float2*)&out[(size_t)(rr + 8) * PC + cc] = o1;
        }
}

// ---------------------------------------------------------------------------
extern "C" void kernel_launch(void* const* d_in, const int* in_sizes, int n_in,
                              void* d_out, int out_size) {
    const float* x  = (const float*)d_in[0];
    const float* wq = (const float*)d_in[1];
    const float* wk = (const float*)d_in[2];
    const float* wv = (const float*)d_in[3];
    const float* rw = (const float*)d_in[4];
    const float* rb = (const float*)d_in[5];
    const float* gm = (const float*)d_in[6];
    const float* bt = (const float*)d_in[7];
    const float* pw = (const float*)d_in[8];
    const float* pb = (const float*)d_in[9];
    float* out = (float*)d_out;
    float* attn_out = out + (size_t)PB * PN * PC;

    cudaFuncSetAttribute(qk_mma_kernel, cudaFuncAttributeMaxDynamicSharedMemorySize, QK_SMEM);
    cudaFuncSetAttribute(av_mma_kernel, cudaFuncAttributeMaxDynamicSharedMemorySize, AV_SMEM);
    cudaFuncSetAttribute(proj_mma_kernel, cudaFuncAttributeMaxDynamicSharedMemorySize, PJ_SMEM);

    zero_stats_kernel<<<1, 32>>>();
    conv_qkv_kernel<<<PB * PN, 256>>>(x, wq, wk, wv);
    qk_mma_kernel<<<dim3(8, 8, 64), 256, QK_SMEM>>>();
    softmax_mix_kernel<<<PB * PN, 256>>>(rw, rb);
    finalize_kernel<<<1, 32>>>(gm, bt);
    av_mma_kernel<<<dim3(8, 64), 256, AV_SMEM>>>(attn_out);
    proj_mma_kernel<<<dim3(6, 64), 256, PJ_SMEM>>>(pw, pb, out);
}

// round 6
// speedup vs baseline: 2.9317x; 1.6634x over previous
#include <cuda_runtime.h>
#include <cuda_bf16.h>
#include <math.h>
#include <cstdint>

#define PB 8
#define PN 1024
#define PC 768
#define PH 8
#define PD 96
#define PM 1024

// bf16 hi/lo operand arrays (split done once by producers)
__device__ __nv_bfloat16 g_qh[(size_t)PB*PN*PC], g_ql[(size_t)PB*PN*PC];
__device__ __nv_bfloat16 g_kh[(size_t)PB*PN*PC], g_kl[(size_t)PB*PN*PC];
__device__ float         g_v [(size_t)PB*PN*PC];
__device__ float         g_S [(size_t)PB*PH*PN*PM];        // fp32 scores (qk -> softmax)
__device__ __nv_bfloat16 g_ph[(size_t)PB*PH*PN*PM];        // mixed attn hi
__device__ __nv_bfloat16 g_pl[(size_t)PB*PH*PN*PM];        // mixed attn lo
__device__ __nv_bfloat16 g_vth[(size_t)PB*PH*PD*PM], g_vtl[(size_t)PB*PH*PD*PM]; // V^T
__device__ float         g_vsum[PB*PH*PD];                  // colsum of V per (bg,d)
__device__ __nv_bfloat16 g_ohh[(size_t)PB*PN*PC], g_ohl[(size_t)PB*PN*PC];       // oh (b,n,c)
__device__ __nv_bfloat16 g_pwh[(size_t)PC*PC], g_pwl[(size_t)PC*PC];
__device__ double g_stats[16];
__device__ float  g_norm[16];

// ============================ helpers ======================================
__device__ __forceinline__ uint32_t smem_u32(const void* p) {
    uint32_t a;
    asm("{ .reg .u64 t; cvta.to.shared.u64 t, %1; cvt.u32.u64 %0, t; }"
        : "=r"(a) : "l"(p));
    return a;
}
__device__ __forceinline__ void ldsm4(uint32_t addr, uint32_t* r) {
    asm volatile("ldmatrix.sync.aligned.m8n8.x4.shared.b16 {%0,%1,%2,%3}, [%4];"
                 : "=r"(r[0]), "=r"(r[1]), "=r"(r[2]), "=r"(r[3]) : "r"(addr));
}
__device__ __forceinline__ void mma16816(float* d, const uint32_t* a, const uint32_t* b) {
    asm volatile("mma.sync.aligned.m16n8k16.row.col.f32.bf16.bf16.f32 "
                 "{%0,%1,%2,%3}, {%4,%5,%6,%7}, {%8,%9}, {%0,%1,%2,%3};"
                 : "+f"(d[0]), "+f"(d[1]), "+f"(d[2]), "+f"(d[3])
                 : "r"(a[0]), "r"(a[1]), "r"(a[2]), "r"(a[3]), "r"(b[0]), "r"(b[1]));
}
#define CP16(dst, src) asm volatile("cp.async.cg.shared.global [%0], [%1], 16;" :: "r"(dst), "l"(src))
#define CP_COMMIT()    asm volatile("cp.async.commit_group;")
#define CP_WAIT0()     asm volatile("cp.async.wait_group 0;" ::: "memory")
#define CP_WAIT1()     asm volatile("cp.async.wait_group 1;" ::: "memory")

__device__ __forceinline__ void split2(float x, float y, uint32_t& hi, uint32_t& lo) {
    __nv_bfloat16 hx = __float2bfloat16_rn(x), hy = __float2bfloat16_rn(y);
    __nv_bfloat16 lx = __float2bfloat16_rn(x - __bfloat162float(hx));
    __nv_bfloat16 ly = __float2bfloat16_rn(y - __bfloat162float(hy));
    hi = (uint32_t)__bfloat16_as_ushort(hx) | ((uint32_t)__bfloat16_as_ushort(hy) << 16);
    lo = (uint32_t)__bfloat16_as_ushort(lx) | ((uint32_t)__bfloat16_as_ushort(ly) << 16);
}
__device__ __forceinline__ void split1(float x, __nv_bfloat16& h, __nv_bfloat16& l) {
    h = __float2bfloat16_rn(x);
    l = __float2bfloat16_rn(x - __bfloat162float(h));
}
// reconstruct 4 floats from packed hi/lo bf16x2 pairs
__device__ __forceinline__ float4 rec4(uint2 h, uint2 l) {
    float4 f;
    f.x = __uint_as_float((h.x & 0xFFFFu) << 16) + __uint_as_float((l.x & 0xFFFFu) << 16);
    f.y = __uint_as_float(h.x & 0xFFFF0000u)     + __uint_as_float(l.x & 0xFFFF0000u);
    f.z = __uint_as_float((h.y & 0xFFFFu) << 16) + __uint_as_float((l.y & 0xFFFFu) << 16);
    f.w = __uint_as_float(h.y & 0xFFFF0000u)     + __uint_as_float(l.y & 0xFFFF0000u);
    return f;
}

// ---------------------------------------------------------------------------
__global__ void zero_stats_kernel() {
    int tid = threadIdx.x;
    if (tid < 16) g_stats[tid] = 0.0;
    for (int i = tid; i < PB * PH * PD; i += 256) g_vsum[i] = 0.f;
}

// ---------------------------------------------------------------------------
// Per-token 3x3 SAME convs; writes q(scaled)/k as bf16 hi/lo, v as fp32.
__global__ void conv_qkv_kernel(const float* __restrict__ x,
                                const float* __restrict__ wq,
                                const float* __restrict__ wk,
                                const float* __restrict__ wv) {
    __shared__ float simg[3][16][16];
    __shared__ float sw[3][81];
    int img = blockIdx.x;
    int tid = threadIdx.x;
    for (int e = tid; e < 768; e += 256)
        ((float*)simg)[e] = x[(size_t)img * 768 + e];
    if (tid < 81) { sw[0][tid] = wq[tid]; sw[1][tid] = wk[tid]; sw[2][tid] = wv[tid]; }
    __syncthreads();
    int i = tid >> 4, j = tid & 15;
    float out[3][3];
    #pragma unroll
    for (int a = 0; a < 3; a++)
        #pragma unroll
        for (int c = 0; c < 3; c++) out[a][c] = 0.f;
    #pragma unroll
    for (int ci = 0; ci < 3; ci++)
        #pragma unroll
        for (int di = 0; di < 3; di++) {
            int ii = i + di - 1;
            if (ii < 0 || ii > 15) continue;
            #pragma unroll
            for (int dj = 0; dj < 3; dj++) {
                int jj = j + dj - 1;
                if (jj < 0 || jj > 15) continue;
                float pix = simg[ci][ii][jj];
                int wi = ci * 9 + di * 3 + dj;
                #pragma unroll
                for (int co = 0; co < 3; co++) {
                    out[0][co] += pix * sw[0][co * 27 + wi];
                    out[1][co] += pix * sw[1][co * 27 + wi];
                    out[2][co] += pix * sw[2][co * 27 + wi];
                }
            }
        }
    const float scale = 0.10206207261596577f;  // 96^-0.5 (folded into q)
    #pragma unroll
    for (int co = 0; co < 3; co++) {
        int c = co * 256 + i * 16 + j;
        size_t o = (size_t)img * 768 + c;
        __nv_bfloat16 h, l;
        split1(out[0][co] * scale, h, l);
        g_qh[o] = h; g_ql[o] = l;
        split1(out[1][co], h, l);
        g_kh[o] = h; g_kl[o] = l;
        g_v[o] = out[2][co];
    }
}

// ---------------------------------------------------------------------------
// V transpose: v (b,m,c) fp32 -> vt hi/lo [(bg), d, m] bf16 + colsums.
__global__ void vt_kernel() {
    __shared__ float sm[64 * 97];
    __shared__ float svs[96];
    int tid = threadIdx.x;
    int mc = blockIdx.x, bg = blockIdx.y;
    int b = bg >> 3, g = bg & 7;
    int m0 = mc * 64;
    if (tid < 96) svs[tid] = 0.f;
    #pragma unroll
    for (int i = 0; i < 6; i++) {
        int idx = tid + i * 256;
        int mr = idx / 24, d4 = (idx % 24) * 4;
        float4 f = *(const float4*)&g_v[(size_t)(b * 1024 + m0 + mr) * PC + g * PD + d4];
        sm[mr * 97 + d4 + 0] = f.x;
        sm[mr * 97 + d4 + 1] = f.y;
        sm[mr * 97 + d4 + 2] = f.z;
        sm[mr * 97 + d4 + 3] = f.w;
    }
    __syncthreads();
    #pragma unroll
    for (int i = 0; i < 12; i++) {
        int idx = tid + i * 256;
        int d = idx >> 5, m2 = idx & 31;
        float v0 = sm[(2 * m2) * 97 + d];
        float v1 = sm[(2 * m2 + 1) * 97 + d];
        uint32_t h, l;
        split2(v0, v1, h, l);
        size_t o = (size_t)bg * PD * PM + (size_t)d * PM + m0 + 2 * m2;
        *(uint32_t*)&g_vth[o] = h;
        *(uint32_t*)&g_vtl[o] = l;
        atomicAdd(&svs[d], v0 + v1);
    }
    __syncthreads();
    if (tid < 96) atomicAdd(&g_vsum[bg * 96 + tid], svs[tid]);
}

// ---------------------------------------------------------------------------
// proj weight split
__global__ void pw_split_kernel(const float* __restrict__ pw) {
    int idx = blockIdx.x * 256 + threadIdx.x;      // one float4 per thread
    float4 f = *(const float4*)&pw[(size_t)idx * 4];
    uint32_t h0, l0, h1, l1;
    split2(f.x, f.y, h0, l0);
    split2(f.z, f.w, h1, l1);
    *(uint2*)&g_pwh[(size_t)idx * 4] = make_uint2(h0, h1);
    *(uint2*)&g_pwl[(size_t)idx * 4] = make_uint2(l0, l1);
}

// ===========================================================================
// qk: 128x128 tile, K=96, pure cp.async staging, 2 CTAs/SM.
// ===========================================================================
#define QK_SA 104
#define QK_TILE (128 * QK_SA * 2)         // 26624
#define QK_SMEM (4 * QK_TILE)             // 106496

__global__ void __launch_bounds__(256, 2) qk_mma_kernel() {
    extern __shared__ char smem[];
    uint32_t sb = smem_u32(smem);
    uint32_t uAHI = sb, uALO = sb + QK_TILE, uBHI = sb + 2 * QK_TILE, uBLO = sb + 3 * QK_TILE;
    int tid = threadIdx.x, wid = tid >> 5, lane = tid & 31;
    int mt = blockIdx.x, nt = blockIdx.y, bh = blockIdx.z;
    int b = bh >> 3, h = bh & 7;
    int n0 = nt * 128, m0 = mt * 128;

    // stage: 128 rows x 12 x 16B per tile, 4 tiles
    #pragma unroll
    for (int i = 0; i < 6; i++) {
        int idx = tid + i * 256;
        int row = idx / 12, c = idx % 12;
        uint32_t so = (uint32_t)(row * QK_SA) * 2 + c * 16;
        size_t qa = (size_t)(b * 1024 + n0 + row) * PC + h * PD + c * 8;
        size_t ka = (size_t)(b * 1024 + m0 + row) * PC + h * PD + c * 8;
        CP16(uAHI + so, g_qh + qa);
        CP16(uALO + so, g_ql + qa);
        CP16(uBHI + so, g_kh + ka);
        CP16(uBLO + so, g_kl + ka);
    }
    CP_COMMIT();
    CP_WAIT0();
    __syncthreads();

    int lr = lane & 7;
    int a_row = lr + ((lane >> 3) & 1) * 8, a_k = (lane >> 4) * 8;
    int b_row = lr + (lane >> 4) * 8,       b_k = ((lane >> 3) & 1) * 8;
    int wr = (wid >> 1) * 32, wc = (wid & 1) * 64;

    float acc[2][8][4] = {};
    #pragma unroll
    for (int ks = 0; ks < 6; ks++) {
        int k0 = ks * 16;
        uint32_t ah[2][4], al[2][4];
        #pragma unroll
        for (int mf = 0; mf < 2; mf++) {
            uint32_t off = (uint32_t)((wr + mf * 16 + a_row) * QK_SA + k0 + a_k) * 2;
            ldsm4(uAHI + off, ah[mf]);
            ldsm4(uALO + off, al[mf]);
        }
        #pragma unroll
        for (int np = 0; np < 4; np++) {
            uint32_t off = (uint32_t)((wc + np * 16 + b_row) * QK_SA + k0 + b_k) * 2;
            uint32_t bh4[4], bl4[4];
            ldsm4(uBHI + off, bh4);
            ldsm4(uBLO + off, bl4);
            #pragma unroll
            for (int mf = 0; mf < 2; mf++)
                #pragma unroll
                for (int sub = 0; sub < 2; sub++) {
                    float* d = acc[mf][np * 2 + sub];
                    mma16816(d, ah[mf], &bh4[sub * 2]);
                    mma16816(d, ah[mf], &bl4[sub * 2]);
                    mma16816(d, al[mf], &bh4[sub * 2]);
                }
        }
    }

    float* Sb = g_S + ((size_t)bh * PN + n0) * PM + m0;
    int r0 = wr + (lane >> 2);
    int cbase = wc + 2 * (lane & 3);
    #pragma unroll
    for (int mf = 0; mf < 2; mf++)
        #pragma unroll
        for (int nf = 0; nf < 8; nf++) {
            int rr = r0 + mf * 16, cc = cbase + nf * 8;
            *(float2*)&Sb[(size_t)rr * PM + cc]       = make_float2(acc[mf][nf][0], acc[mf][nf][1]);
            *(float2*)&Sb[(size_t)(rr + 8) * PM + cc] = make_float2(acc[mf][nf][2], acc[mf][nf][3]);
        }
}

// ---------------------------------------------------------------------------
// softmax + head-mix + BN stats; writes mixed attn as bf16 hi/lo.
__global__ void __launch_bounds__(256) softmax_mix_kernel(const float* __restrict__ rw,
                                                          const float* __restrict__ rb) {
    __shared__ float red[8][8];
    __shared__ float smax[8];
    __shared__ float sinv[8];
    __shared__ float wsc[8][8];
    __shared__ float sbias[8];
    __shared__ float ssum[8], ssq[8];
    int bn = blockIdx.x;
    int b = bn >> 10, n = bn & 1023;
    int tid = threadIdx.x;
    int lane = tid & 31, warp = tid >> 5;
    if (tid < 8) { sbias[tid] = rb[tid]; ssum[tid] = 0.f; ssq[tid] = 0.f; }

    float4 r[8];
    #pragma unroll
    for (int h = 0; h < 8; h++)
        r[h] = *(const float4*)&g_S[(((size_t)(b * 8 + h)) * PN + n) * PM + tid * 4];

    float mx[8];
    #pragma unroll
    for (int h = 0; h < 8; h++) {
        mx[h] = fmaxf(fmaxf(r[h].x, r[h].y), fmaxf(r[h].z, r[h].w));
        #pragma unroll
        for (int off = 16; off; off >>= 1)
            mx[h] = fmaxf(mx[h], __shfl_xor_sync(0xffffffffu, mx[h], off));
    }
    if (lane == 0)
        #pragma unroll
        for (int h = 0; h < 8; h++) red[warp][h] = mx[h];
    __syncthreads();
    if (tid < 8) {
        float m2 = red[0][tid];
        #pragma unroll
        for (int w = 1; w < 8; w++) m2 = fmaxf(m2, red[w][tid]);
        smax[tid] = m2;
    }
    __syncthreads();

    float sm[8];
    #pragma unroll
    for (int h = 0; h < 8; h++) {
        float m2 = smax[h];
        r[h].x = __expf(r[h].x - m2);
        r[h].y = __expf(r[h].y - m2);
        r[h].z = __expf(r[h].z - m2);
        r[h].w = __expf(r[h].w - m2);
        sm[h] = r[h].x + r[h].y + r[h].z + r[h].w;
        #pragma unroll
        for (int off = 16; off; off >>= 1)
            sm[h] += __shfl_xor_sync(0xffffffffu, sm[h], off);
    }
    if (lane == 0)
        #pragma unroll
        for (int h = 0; h < 8; h++) red[warp][h] = sm[h];
    __syncthreads();
    if (tid < 8) {
        float t = 0.f;
        #pragma unroll
        for (int w = 0; w < 8; w++) t += red[w][tid];
        sinv[tid] = 1.f / t;
    }
    __syncthreads();
    if (tid < 64) wsc[tid >> 3][tid & 7] = rw[tid] * sinv[tid & 7];
    __syncthreads();

    float ls[8], lq[8];
    #pragma unroll
    for (int g = 0; g < 8; g++) {
        float4 o;
        o.x = sbias[g]; o.y = sbias[g]; o.z = sbias[g]; o.w = sbias[g];
        #pragma unroll
        for (int h = 0; h < 8; h++) {
            float w = wsc[g][h];
            o.x += w * r[h].x; o.y += w * r[h].y;
            o.z += w * r[h].z; o.w += w * r[h].w;
        }
        size_t base = (((size_t)(b * 8 + g)) * PN + n) * PM + tid * 4;
        uint32_t h0, l0, h1, l1;
        split2(o.x, o.y, h0, l0);
        split2(o.z, o.w, h1, l1);
        *(uint2*)&g_ph[base] = make_uint2(h0, h1);
        *(uint2*)&g_pl[base] = make_uint2(l0, l1);
        ls[g] = o.x + o.y + o.z + o.w;
        lq[g] = o.x * o.x + o.y * o.y + o.z * o.z + o.w * o.w;
    }
    #pragma unroll
    for (int g = 0; g < 8; g++) {
        #pragma unroll
        for (int off = 16; off; off >>= 1) {
            ls[g] += __shfl_xor_sync(0xffffffffu, ls[g], off);
            lq[g] += __shfl_xor_sync(0xffffffffu, lq[g], off);
        }
        if (lane == 0) { atomicAdd(&ssum[g], ls[g]); atomicAdd(&ssq[g], lq[g]); }
    }
    __syncthreads();
    if (tid < 8) {
        atomicAdd(&g_stats[tid], (double)ssum[tid]);
        atomicAdd(&g_stats[8 + tid], (double)ssq[tid]);
    }
}

// ---------------------------------------------------------------------------
__global__ void finalize_kernel(const float* __restrict__ gamma,
                                const float* __restrict__ beta) {
    int g = threadIdx.x;
    if (g < 8) {
        double cnt = 8388608.0;
        double mean = g_stats[g] / cnt;
        double var = g_stats[8 + g] / cnt - mean * mean;
        double invstd = rsqrt(var + 1e-5);
        double A = invstd * (double)gamma[g];
        g_norm[g] = (float)A;
        g_norm[8 + g] = (float)((double)beta[g] - mean * A);
    }
}

// ===========================================================================
// av: P@V via cp.async double-buffered chunks (m=64, 16 chunks).
// Epilogue folds BN: oh = Ag*acc + Bg*vsum. attn_out reconstructed from smem.
// ===========================================================================
#define AV_SA 72
#define AV_A_HI 0
#define AV_A_LO 18432
#define AV_B_HI 36864
#define AV_B_LO 50688
#define AV_STAGE 64512
#define AV_SMEM (2 * AV_STAGE)            // 129024

__device__ __forceinline__ void av_stage(uint32_t bufb, int bg, int n0, int m0, int tid) {
    #pragma unroll
    for (int i = 0; i < 4; i++) {
        int idx = tid + i * 256;
        int row = idx >> 3, c = idx & 7;
        size_t src = (size_t)(bg * 1024 + n0 + row) * PM + m0 + c * 8;
        uint32_t so = (uint32_t)(row * AV_SA) * 2 + c * 16;
        CP16(bufb + AV_A_HI + so, g_ph + src);
        CP16(bufb + AV_A_LO + so, g_pl + src);
    }
    #pragma unroll
    for (int i = 0; i < 3; i++) {
        int idx = tid + i * 256;
        int row = idx >> 3, c = idx & 7;
        size_t src = (size_t)bg * PD * PM + (size_t)row * PM + m0 + c * 8;
        uint32_t so = (uint32_t)(row * AV_SA) * 2 + c * 16;
        CP16(bufb + AV_B_HI + so, g_vth + src);
        CP16(bufb + AV_B_LO + so, g_vtl + src);
    }
    CP_COMMIT();
}

__global__ void __launch_bounds__(256) av_mma_kernel(float* __restrict__ attn_out) {
    extern __shared__ char smem[];
    uint32_t sb = smem_u32(smem);
    int tid = threadIdx.x, wid = tid >> 5, lane = tid & 31;
    int nt = blockIdx.x, bg = blockIdx.y;
    int b = bg >> 3, g = bg & 7;
    int n0 = nt * 128;
    float Ag = g_norm[g], Bg = g_norm[8 + g];

    int lr = lane & 7;
    int a_row = lr + ((lane >> 3) & 1) * 8, a_k = (lane >> 4) * 8;
    int b_row = lr + (lane >> 4) * 8,       b_k = ((lane >> 3) & 1) * 8;
    int wr = (wid >> 1) * 32, wc = (wid & 1) * 48;

    av_stage(sb, bg, n0, 0, tid);

    float acc[2][6][4] = {};
    for (int ch = 0; ch < 16; ch++) {
        uint32_t bufb = sb + (ch & 1) * AV_STAGE;
        if (ch + 1 < 16) {
            av_stage(sb + ((ch + 1) & 1) * AV_STAGE, bg, n0, (ch + 1) * 64, tid);
            CP_WAIT1();
        } else {
            CP_WAIT0();
        }
        __syncthreads();

        // attn_out writeback from staged tiles
        int m0 = ch * 64;
        #pragma unroll
        for (int i = 0; i < 8; i++) {
            int idx = tid + i * 256;
            int row = idx >> 4, col4 = (idx & 15) * 4;
            uint32_t so = (uint32_t)(row * AV_SA + col4) * 2;
            uint2 hw = *(uint2*)(smem + (bufb - sb) + AV_A_HI + so);
            uint2 lw = *(uint2*)(smem + (bufb - sb) + AV_A_LO + so);
            float4 v = rec4(hw, lw);
            v.x = v.x * Ag + Bg; v.y = v.y * Ag + Bg;
            v.z = v.z * Ag + Bg; v.w = v.w * Ag + Bg;
            *(float4*)&attn_out[(size_t)(bg * 1024 + n0 + row) * PM + m0 + col4] = v;
        }

        #pragma unroll
        for (int ks = 0; ks < 4; ks++) {
            int k0 = ks * 16;
            uint32_t ah[2][4], al[2][4];
            #pragma unroll
            for (int mf = 0; mf < 2; mf++) {
                uint32_t off = (uint32_t)((wr + mf * 16 + a_row) * AV_SA + k0 + a_k) * 2;
                ldsm4(bufb + AV_A_HI + off, ah[mf]);
                ldsm4(bufb + AV_A_LO + off, al[mf]);
            }
            #pragma unroll
            for (int np = 0; np < 3; np++) {
                uint32_t off = (uint32_t)((wc + np * 16 + b_row) * AV_SA + k0 + b_k) * 2;
                uint32_t bh4[4], bl4[4];
                ldsm4(bufb + AV_B_HI + off, bh4);
                ldsm4(bufb + AV_B_LO + off, bl4);
                #pragma unroll
                for (int mf = 0; mf < 2; mf++)
                    #pragma unroll
                    for (int sub = 0; sub < 2; sub++) {
                        float* d = acc[mf][np * 2 + sub];
                        mma16816(d, ah[mf], &bh4[sub * 2]);
                        mma16816(d, ah[mf], &bl4[sub * 2]);
                        mma16816(d, al[mf], &bh4[sub * 2]);
                    }
            }
        }
        __syncthreads();
    }

    // epilogue: oh = Ag*acc + Bg*vsum; write bf16 hi/lo in (b,n,c) layout
    int r0 = wr + (lane >> 2);
    int cbase = wc + 2 * (lane & 3);
    #pragma unroll
    for (int mf = 0; mf < 2; mf++)
        #pragma unroll
        for (int nf = 0; nf < 6; nf++) {
            int cc = cbase + nf * 8;
            float vs0 = g_vsum[bg * 96 + cc], vs1 = g_vsum[bg * 96 + cc + 1];
            #pragma unroll
            for (int half = 0; half < 2; half++) {
                int rr = r0 + mf * 16 + half * 8;
                float o0 = Ag * acc[mf][nf][half * 2 + 0] + Bg * vs0;
                float o1 = Ag * acc[mf][nf][half * 2 + 1] + Bg * vs1;
                uint32_t hw, lw;
                split2(o0, o1, hw, lw);
                size_t off = (size_t)(b * 1024 + n0 + rr) * PC + g * PD + cc;
                *(uint32_t*)&g_ohh[off] = hw;
                *(uint32_t*)&g_ohl[off] = lw;
            }
        }
}

// ===========================================================================
// proj: 128x128 tile, K=768 in 12 chunks of 64, cp.async double-buffered.
// ===========================================================================
#define PJ_SA 72
#define PJ_A_HI 0
#define PJ_A_LO 18432
#define PJ_B_HI 36864
#define PJ_B_LO 55296
#define PJ_STAGE 73728
#define PJ_SMEM (2 * PJ_STAGE)            // 147456

__device__ __forceinline__ void pj_stage(uint32_t bufb, int r0b, int c0, int kc, int tid) {
    #pragma unroll
    for (int i = 0; i < 4; i++) {
        int idx = tid + i * 256;
        int row = idx >> 3, c = idx & 7;
        size_t sa = (size_t)(r0b + row) * PC + kc + c * 8;
        size_t sw = (size_t)(c0 + row) * PC + kc + c * 8;
        uint32_t so = (uint32_t)(row * PJ_SA) * 2 + c * 16;
        CP16(bufb + PJ_A_HI + so, g_ohh + sa);
        CP16(bufb + PJ_A_LO + so, g_ohl + sa);
        CP16(bufb + PJ_B_HI + so, g_pwh + sw);
        CP16(bufb + PJ_B_LO + so, g_pwl + sw);
    }
    CP_COMMIT();
}

__global__ void __launch_bounds__(256) proj_mma_kernel(const float* __restrict__ pb,
                                                       float* __restrict__ out) {
    extern __shared__ char smem[];
    uint32_t sb = smem_u32(smem);
    int tid = threadIdx.x, wid = tid >> 5, lane = tid & 31;
    int ct = blockIdx.x, rt = blockIdx.y;
    int r0b = rt * 128, c0 = ct * 128;

    int lr = lane & 7;
    int a_row = lr + ((lane >> 3) & 1) * 8, a_k = (lane >> 4) * 8;
    int b_row = lr + (lane >> 4) * 8,       b_k = ((lane >> 3) & 1) * 8;
    int wr = (wid >> 1) * 32, wc = (wid & 1) * 64;

    pj_stage(sb, r0b, c0, 0, tid);

    float acc[2][8][4] = {};
    for (int ch = 0; ch < 12; ch++) {
        uint32_t bufb = sb + (ch & 1) * PJ_STAGE;
        if (ch + 1 < 12) {
            pj_stage(sb + ((ch + 1) & 1) * PJ_STAGE, r0b, c0, (ch + 1) * 64, tid);
            CP_WAIT1();
        } else {
            CP_WAIT0();
        }
        __syncthreads();

        #pragma unroll
        for (int ks = 0; ks < 4; ks++) {
            int k0 = ks * 16;
            uint32_t ah[2][4], al[2][4];
            #pragma unroll
            for (int mf = 0; mf < 2; mf++) {
                uint32_t off = (uint32_t)((wr + mf * 16 + a_row) * PJ_SA + k0 + a_k) * 2;
                ldsm4(bufb + PJ_A_HI + off, ah[mf]);
                ldsm4(bufb + PJ_A_LO + off, al[mf]);
            }
            #pragma unroll
            for (int np = 0; np < 4; np++) {
                uint32_t off = (uint32_t)((wc + np * 16 + b_row) * PJ_SA + k0 + b_k) * 2;
                uint32_t bh4[4], bl4[4];
                ldsm4(bufb + PJ_B_HI + off, bh4);
                ldsm4(bufb + PJ_B_LO + off, bl4);
                #pragma unroll
                for (int mf = 0; mf < 2; mf++)
                    #pragma unroll
                    for (int sub = 0; sub < 2; sub++) {
                        float* d = acc[mf][np * 2 + sub];
                        mma16816(d, ah[mf], &bh4[sub * 2]);
                        mma16816(d, ah[mf], &bl4[sub * 2]);
                        mma16816(d, al[mf], &bh4[sub * 2]);
                    }
            }
        }
        __syncthreads();
    }

    int r0 = wr + (lane >> 2);
    int cbase = wc + 2 * (lane & 3);
    #pragma unroll
    for (int mf = 0; mf < 2; mf++)
        #pragma unroll
        for (int nf = 0; nf < 8; nf++) {
            int rr = r0b + r0 + mf * 16, cc = c0 + cbase + nf * 8;
            float2 o0 = make_float2(acc[mf][nf][0] + pb[cc], acc[mf][nf][1] + pb[cc + 1]);
            float2 o1 = make_float2(acc[mf][nf][2] + pb[cc], acc[mf][nf][3] + pb[cc + 1]);
            *(float2*)&out[(size_t)rr * PC + cc] = o0;
            *(float2*)&out[(size_t)(rr + 8) * PC + cc] = o1;
        }
}

// ---------------------------------------------------------------------------
extern "C" void kernel_launch(void* const* d_in, const int* in_sizes, int n_in,
                              void* d_out, int out_size) {
    const float* x  = (const float*)d_in[0];
    const float* wq = (const float*)d_in[1];
    const float* wk = (const float*)d_in[2];
    const float* wv = (const float*)d_in[3];
    const float* rw = (const float*)d_in[4];
    const float* rb = (const float*)d_in[5];
    const float* gm = (const float*)d_in[6];
    const float* bt = (const float*)d_in[7];
    const float* pw = (const float*)d_in[8];
    const float* pb = (const float*)d_in[9];
    float* out = (float*)d_out;
    float* attn_out = out + (size_t)PB * PN * PC;

    cudaFuncSetAttribute(qk_mma_kernel, cudaFuncAttributeMaxDynamicSharedMemorySize, QK_SMEM);
    cudaFuncSetAttribute(av_mma_kernel, cudaFuncAttributeMaxDynamicSharedMemorySize, AV_SMEM);
    cudaFuncSetAttribute(proj_mma_kernel, cudaFuncAttributeMaxDynamicSharedMemorySize, PJ_SMEM);

    zero_stats_kernel<<<1, 256>>>();
    conv_qkv_kernel<<<PB * PN, 256>>>(x, wq, wk, wv);
    vt_kernel<<<dim3(16, 64), 256>>>();
    pw_split_kernel<<<576, 256>>>(pw);
    qk_mma_kernel<<<dim3(8, 8, 64), 256, QK_SMEM>>>();
    softmax_mix_kernel<<<PB * PN, 256>>>(rw, rb);
    finalize_kernel<<<1, 32>>>(gm, bt);
    av_mma_kernel<<<dim3(8, 64), 256, AV_SMEM>>>(attn_out);
    proj_mma_kernel<<<dim3(6, 64), 256, PJ_SMEM>>>(pb, out);
}